// round 5
// baseline (speedup 1.0000x reference)
#include <cuda_runtime.h>
#include <cstdint>

#define NB 16
#define CIN 64
#define HH 112
#define WW 112
#define COUT 128
#define HP 114                       // padded spatial (1-pixel halo)
#define HP2 (HP * HP)                // 12996
#define MPAD (NB * HP2)              // 207936 GEMM rows
#define KPT 192                      // K per tap (3 powers x 64 ci)
#define KTOT 1728                    // 9 taps * 192
#define NCHUNK 108                   // 1728 / 16
#define STAGES 4
#define PITCH 20                     // floats per smem tile row (80B, 16B-aligned)
#define MT 256                       // CTA M tile
#define NT 128                       // CTA N tile
#define A_TILE_F (MT * PITCH)
#define STAGE_F ((MT + NT) * PITCH)  // 7680 floats = 30720 B
#define SMEM_BYTES (STAGES * STAGE_F * 4)  // 122880

// scratch: padded tf32 powers matrix and tf32 weight matrix (16B aligned for cp.async)
__device__ __align__(128) float g_P[(size_t)MPAD * KPT];   // [m][q*64+ci]
__device__ __align__(128) float g_B[(size_t)COUT * KTOT];  // [co][tap*192+q*64+ci]

// ---------------------------------------------------------------------------
// PTX helpers (base PTX only — harness targets sm_103 family, no tcgen05.ld)
// ---------------------------------------------------------------------------
__device__ __forceinline__ uint32_t smem_u32(const void* p) {
    uint32_t a;
    asm("{ .reg .u64 t; cvta.to.shared.u64 t, %1; cvt.u32.u64 %0, t; }"
        : "=r"(a) : "l"(p));
    return a;
}

__device__ __forceinline__ void cp16(uint32_t dst, const void* src, uint32_t sz) {
    asm volatile("cp.async.cg.shared.global [%0], [%1], 16, %2;"
                 :: "r"(dst), "l"(src), "r"(sz) : "memory");
}

#define CP_COMMIT() asm volatile("cp.async.commit_group;" ::: "memory")
#define CP_WAIT2()  asm volatile("cp.async.wait_group 2;" ::: "memory")

#define LDSM_X4(r0, r1, r2, r3, addr)                                         \
    asm volatile("ldmatrix.sync.aligned.m8n8.x4.shared.b16 {%0,%1,%2,%3}, [%4];" \
                 : "=r"(r0), "=r"(r1), "=r"(r2), "=r"(r3) : "r"(addr))

#define LDSM_X2(r0, r1, addr)                                                 \
    asm volatile("ldmatrix.sync.aligned.m8n8.x2.shared.b16 {%0,%1}, [%2];"    \
                 : "=r"(r0), "=r"(r1) : "r"(addr))

#define MMA_TF32(c, a0, a1, a2, a3, b0, b1)                                   \
    asm volatile(                                                             \
        "mma.sync.aligned.m16n8k8.row.col.f32.tf32.tf32.f32 "                 \
        "{%0,%1,%2,%3}, {%4,%5,%6,%7}, {%8,%9}, {%0,%1,%2,%3};"               \
        : "+f"((c)[0]), "+f"((c)[1]), "+f"((c)[2]), "+f"((c)[3])              \
        : "r"(a0), "r"(a1), "r"(a2), "r"(a3), "r"(b0), "r"(b1))

__device__ __forceinline__ float round_tf32(float v) {
    uint32_t t;
    asm("cvt.rna.tf32.f32 %0, %1;" : "=r"(t) : "f"(v));
    return __uint_as_float(t);
}

// ---------------------------------------------------------------------------
// Kernel 1: fused bilinear shift + Maclaurin powers into padded tf32 matrix P.
// Block = (n, hp) row. Thread -> fixed ci = tid&63, wp stride 4. Shift params
// computed once per thread; no div/mod in the hot loops.
// ---------------------------------------------------------------------------
__global__ void __launch_bounds__(256)
pbuild_kernel(const float* __restrict__ x, const float* __restrict__ shifts) {
    __shared__ float sv[CIN][HP + 6];
    const int tid = threadIdx.x;
    const int ci = tid & 63;
    const int wpg = tid >> 6;      // 0..3
    const int hp = blockIdx.x % HP;
    const int n = blockIdx.x / HP;

    // per-thread (per-ci) shift parameters, computed once
    const float sx = shifts[ci * 2 + 0] * 4.0f;
    const float sy = shifts[ci * 2 + 1] * 4.0f;
    const bool row_live = (hp >= 1) && (hp <= HH);

    if (row_live) {
        const int h = hp - 1;
        const float iy = (float)h + sy;
        const float y0f = floorf(iy);
        const float wy = iy - y0f;
        const int y0 = (int)y0f;
        const bool vy0 = (y0 >= 0) && (y0 < HH);
        const bool vy1 = (y0 + 1 >= 0) && (y0 + 1 < HH);
        const float* xp0 = x + ((size_t)(n * CIN + ci) * HH + (vy0 ? y0 : 0)) * WW;
        const float* xp1 = x + ((size_t)(n * CIN + ci) * HH + (vy1 ? y0 + 1 : 0)) * WW;
        const float fy0 = vy0 ? (1.f - wy) : 0.f;
        const float fy1 = vy1 ? wy : 0.f;

#pragma unroll 4
        for (int wp = wpg; wp < HP; wp += 4) {
            float v = 0.f;
            if (wp >= 1 && wp <= WW) {
                const int w = wp - 1;
                const float jx = (float)w + sx;
                const float x0f = floorf(jx);
                const float wx = jx - x0f;
                const int x0 = (int)x0f;
                const bool vx0 = (x0 >= 0) && (x0 < WW);
                const bool vx1 = (x0 + 1 >= 0) && (x0 + 1 < WW);
                float v00 = vx0 ? xp0[x0] : 0.f;
                float v01 = vx1 ? xp0[x0 + 1] : 0.f;
                float v10 = vx0 ? xp1[x0] : 0.f;
                float v11 = vx1 ? xp1[x0 + 1] : 0.f;
                v = fy0 * ((1.f - wx) * v00 + wx * v01)
                  + fy1 * ((1.f - wx) * v10 + wx * v11);
            }
            sv[ci][wp] = v;
        }
    } else {
#pragma unroll 4
        for (int wp = wpg; wp < HP; wp += 4) sv[ci][wp] = 0.f;
    }
    __syncthreads();

    // write powers: coalesced 64-float runs per (q, wp)
    float* pb = g_P + (size_t)blockIdx.x * HP * KPT + ci;
#pragma unroll 4
    for (int wp = wpg; wp < HP; wp += 4) {
        const float v = sv[ci][wp];
        float* p = pb + (size_t)wp * KPT;
        p[0] = round_tf32(v);
        p[64] = round_tf32(v * v);
        p[128] = round_tf32(v * v * v);
    }
}

// ---------------------------------------------------------------------------
// Kernel 2: weight matrix prep, K ordered (tap, q, ci), tf32-rounded
// ---------------------------------------------------------------------------
__global__ void bprep_kernel(const float* __restrict__ w) {
    int idx = blockIdx.x * blockDim.x + threadIdx.x;
    if (idx >= COUT * KTOT) return;
    int co = idx / KTOT;
    int kk = idx % KTOT;
    int tap = kk / KPT;
    int k2 = kk % KPT;
    int q = k2 >> 6;
    int ci = k2 & 63;
    int ky = tap / 3;
    int kx = tap % 3;
    g_B[idx] = round_tf32(
        w[(((size_t)co * (3 * CIN) + q * CIN + ci) * 3 + ky) * 3 + kx]);
}

// ---------------------------------------------------------------------------
// Kernel 3: implicit-GEMM conv via mma.sync tf32 (HMMA).
// CTA: 256(M) x 128(N), K-chunks of 16, 4-stage cp.async pipeline.
// 8 warps as 4(M) x 2(N); warp tile 64x64 (4 mtiles x 8 ntiles of m16n8).
// ---------------------------------------------------------------------------
__global__ void __launch_bounds__(256, 1)
gemm_kernel(const float* __restrict__ bias, float* __restrict__ out) {
    extern __shared__ float smem[];
    const uint32_t sbase = smem_u32(smem);
    const int tid = threadIdx.x;
    const int lane = tid & 31;
    const int wid = tid >> 5;
    const long long m0 = (long long)blockIdx.x * MT;

    const int warpM = (wid >> 1) * 64;
    const int warpN = (wid & 1) * 64;

    // ldmatrix per-thread source coordinates
    const int rowA = ((lane >> 3) & 1) * 8 + (lane & 7);
    const int colA = (lane >> 4) * 4;
    const uint32_t aAddr0 = sbase + (uint32_t)(((warpM + rowA) * PITCH + colA) * 4);
    const int rowB = lane & 7;
    const int colB = ((lane >> 3) & 1) * 4;
    const uint32_t bAddr0 = sbase + (uint32_t)(A_TILE_F * 4) +
                            (uint32_t)(((warpN + rowB) * PITCH + colB) * 4);

    // cp.async per-thread coordinates
    const int rr = tid >> 2;       // 0..63
    const int kc = tid & 3;        // 16B chunk within 16-float row

    float acc[4][8][4];
#pragma unroll
    for (int i = 0; i < 4; ++i)
#pragma unroll
        for (int j = 0; j < 8; ++j)
#pragma unroll
            for (int k = 0; k < 4; ++k) acc[i][j][k] = 0.f;

    // -------- stage loader --------
    auto load_chunk = [&](int c, int s) {
        const int tap = c / 12;
        const int inner = (c % 12) * 16;
        const int toff = (tap / 3 - 1) * HP + (tap % 3 - 1);
        const uint32_t dA = sbase + (uint32_t)(s * STAGE_F * 4);
        const uint32_t dB = dA + (uint32_t)(A_TILE_F * 4);

#pragma unroll
        for (int j = 0; j < 4; ++j) {
            const int r = rr + j * 64;
            long long grow = m0 + r + toff;
            bool ok = (grow >= 0) && (grow < (long long)MPAD);
            const float* src = g_P + (ok ? grow : 0) * KPT + inner + kc * 4;
            cp16(dA + (uint32_t)((r * PITCH + kc * 4) * 4), src, ok ? 16u : 0u);
        }
#pragma unroll
        for (int j = 0; j < 2; ++j) {
            const int r = rr + j * 64;
            cp16(dB + (uint32_t)((r * PITCH + kc * 4) * 4),
                 g_B + (size_t)r * KTOT + c * 16 + kc * 4, 16u);
        }
        CP_COMMIT();
    };

    // prologue: stages 0..2
#pragma unroll
    for (int s = 0; s < STAGES - 1; ++s) load_chunk(s, s);

    // -------- main loop --------
#pragma unroll 1
    for (int c = 0; c < NCHUNK; ++c) {
        const int cpre = c + STAGES - 1;
        if (cpre < NCHUNK) load_chunk(cpre, cpre & 3);
        else CP_COMMIT();
        CP_WAIT2();
        __syncthreads();

        const uint32_t soff = (uint32_t)((c & 3) * STAGE_F * 4);
        const uint32_t sa = aAddr0 + soff;
        const uint32_t sb = bAddr0 + soff;

#pragma unroll
        for (int ks = 0; ks < 2; ++ks) {
            const uint32_t koff = (uint32_t)(ks * 8 * 4);
            uint32_t b0[8], b1[8];
#pragma unroll
            for (int nt = 0; nt < 8; ++nt)
                LDSM_X2(b0[nt], b1[nt], sb + (uint32_t)(nt * 8 * PITCH * 4) + koff);
#pragma unroll
            for (int mt = 0; mt < 4; ++mt) {
                uint32_t a0, a1, a2, a3;
                LDSM_X4(a0, a1, a2, a3, sa + (uint32_t)(mt * 16 * PITCH * 4) + koff);
#pragma unroll
                for (int nt = 0; nt < 8; ++nt)
                    MMA_TF32(acc[mt][nt], a0, a1, a2, a3, b0[nt], b1[nt]);
            }
        }
        __syncthreads();
    }

    // -------- epilogue --------
#pragma unroll
    for (int mt = 0; mt < 4; ++mt) {
#pragma unroll
        for (int half = 0; half < 2; ++half) {
            long long m = m0 + warpM + mt * 16 + (lane >> 2) + half * 8;
            if (m >= (long long)MPAD) continue;
            int mi = (int)m;
            int nb = mi / HP2;
            int rem = mi % HP2;
            int hp = rem / HP;
            int wp = rem % HP;
            if (hp < 1 || hp > HH || wp < 1 || wp > WW) continue;
            float* op = out + (((size_t)nb * COUT) * HH + (hp - 1)) * WW + (wp - 1);
#pragma unroll
            for (int nt = 0; nt < 8; ++nt) {
                int co = warpN + nt * 8 + 2 * (lane & 3);
                op[(size_t)co * (HH * WW)] =
                    acc[mt][nt][half * 2 + 0] + __ldg(bias + co);
                op[(size_t)(co + 1) * (HH * WW)] =
                    acc[mt][nt][half * 2 + 1] + __ldg(bias + co + 1);
            }
        }
    }
}

// ---------------------------------------------------------------------------
extern "C" void kernel_launch(void* const* d_in, const int* in_sizes, int n_in,
                              void* d_out, int out_size) {
    const float* x = (const float*)d_in[0];
    const float* weights = (const float*)d_in[1];
    const float* bias = (const float*)d_in[2];
    const float* shifts = (const float*)d_in[3];
    float* out = (float*)d_out;

    pbuild_kernel<<<NB * HP, 256>>>(x, shifts);
    bprep_kernel<<<(COUT * KTOT + 255) / 256, 256>>>(weights);

    cudaFuncSetAttribute(gemm_kernel,
                         cudaFuncAttributeMaxDynamicSharedMemorySize,
                         SMEM_BYTES);
    const int grid = (MPAD + MT - 1) / MT;  // 813
    gemm_kernel<<<grid, 256, SMEM_BYTES>>>(bias, out);
}

// round 9
// speedup vs baseline: 1.0955x; 1.0955x over previous
#include <cuda_runtime.h>
#include <cstdint>

#define NB 16
#define CIN 64
#define HH 112
#define WW 112
#define COUT 128
#define HP 114                       // padded spatial (1-pixel halo)
#define HP2 (HP * HP)                // 12996
#define MPAD (NB * HP2)              // 207936 GEMM rows
#define KPT 192                      // K per tap (3 powers x 64 ci)
#define KTOT 1728                    // 9 taps * 192
#define KC 32                        // K per pipeline chunk
#define NCHUNK 54                    // 1728 / 32
#define STAGES 3
#define PITCH 36                     // floats per smem tile row (KC=32 + 4 pad)
#define MT 128
#define A_TILE_F (MT * PITCH)
#define STAGE_F (2 * A_TILE_F)       // A + B
#define SMEM_BYTES (STAGES * STAGE_F * 4)  // 110592

// scratch: padded tf32 powers matrix and tf32 weight matrix
__device__ __align__(128) float g_P[(size_t)MPAD * KPT];   // [m][q*64+ci]
__device__ __align__(128) float g_B[(size_t)COUT * KTOT];  // [co][tap*192+q*64+ci]

// ---------------------------------------------------------------------------
// PTX helpers (base PTX only — harness ptxas targets sm_103 family)
// ---------------------------------------------------------------------------
__device__ __forceinline__ uint32_t smem_u32(const void* p) {
    uint32_t a;
    asm("{ .reg .u64 t; cvta.to.shared.u64 t, %1; cvt.u32.u64 %0, t; }"
        : "=r"(a) : "l"(p));
    return a;
}

__device__ __forceinline__ void cp16(uint32_t dst, const void* src, uint32_t sz) {
    asm volatile("cp.async.cg.shared.global [%0], [%1], 16, %2;"
                 :: "r"(dst), "l"(src), "r"(sz) : "memory");
}

#define CP_COMMIT() asm volatile("cp.async.commit_group;" ::: "memory")
#define CP_WAIT1()  asm volatile("cp.async.wait_group 1;" ::: "memory")

#define LDSM_X4(r0, r1, r2, r3, addr)                                         \
    asm volatile("ldmatrix.sync.aligned.m8n8.x4.shared.b16 {%0,%1,%2,%3}, [%4];" \
                 : "=r"(r0), "=r"(r1), "=r"(r2), "=r"(r3) : "r"(addr))

#define LDSM_X2(r0, r1, addr)                                                 \
    asm volatile("ldmatrix.sync.aligned.m8n8.x2.shared.b16 {%0,%1}, [%2];"    \
                 : "=r"(r0), "=r"(r1) : "r"(addr))

#define MMA_TF32(c, a0, a1, a2, a3, b0, b1)                                   \
    asm volatile(                                                             \
        "mma.sync.aligned.m16n8k8.row.col.f32.tf32.tf32.f32 "                 \
        "{%0,%1,%2,%3}, {%4,%5,%6,%7}, {%8,%9}, {%0,%1,%2,%3};"               \
        : "+f"((c)[0]), "+f"((c)[1]), "+f"((c)[2]), "+f"((c)[3])              \
        : "r"(a0), "r"(a1), "r"(a2), "r"(a3), "r"(b0), "r"(b1))

__device__ __forceinline__ float round_tf32(float v) {
    uint32_t t;
    asm("cvt.rna.tf32.f32 %0, %1;" : "=r"(t) : "f"(v));
    return __uint_as_float(t);
}

// ---------------------------------------------------------------------------
// Kernel 1: fused bilinear shift + Maclaurin powers into padded tf32 matrix P.
// Block = (n, hp). Warp owns ci rows (params computed per-ci, not per-elem);
// lanes sweep wp -> coalesced image loads. Pitch 117 -> conflict-free phase 2.
// ---------------------------------------------------------------------------
__global__ void __launch_bounds__(256)
pbuild_kernel(const float* __restrict__ x, const float* __restrict__ shifts) {
    __shared__ float sv[CIN][HP + 3];   // 117 mod 32 = 21, odd -> no conflicts
    const int tid = threadIdx.x;
    const int lane = tid & 31;
    const int wid = tid >> 5;
    const int hp = blockIdx.x % HP;
    const int n = blockIdx.x / HP;
    const bool row_live = (hp >= 1) && (hp <= HH);

    for (int ci = wid; ci < CIN; ci += 8) {
        if (row_live) {
            const float sx = shifts[ci * 2 + 0] * 4.0f;
            const float sy = shifts[ci * 2 + 1] * 4.0f;
            const float iy = (float)(hp - 1) + sy;
            const float y0f = floorf(iy);
            const float wy = iy - y0f;
            const int y0 = (int)y0f;
            const bool vy0 = (y0 >= 0) && (y0 < HH);
            const bool vy1 = (y0 + 1 >= 0) && (y0 + 1 < HH);
            const float* xp0 =
                x + ((size_t)(n * CIN + ci) * HH + (vy0 ? y0 : 0)) * WW;
            const float* xp1 =
                x + ((size_t)(n * CIN + ci) * HH + (vy1 ? y0 + 1 : 0)) * WW;
            const float fy0 = vy0 ? (1.f - wy) : 0.f;
            const float fy1 = vy1 ? wy : 0.f;

            for (int wp = lane; wp < HP; wp += 32) {
                float v = 0.f;
                if (wp >= 1 && wp <= WW) {
                    const float jx = (float)(wp - 1) + sx;
                    const float x0f = floorf(jx);
                    const float wx = jx - x0f;
                    const int x0 = (int)x0f;
                    const bool vx0 = (x0 >= 0) && (x0 < WW);
                    const bool vx1 = (x0 + 1 >= 0) && (x0 + 1 < WW);
                    float v00 = vx0 ? xp0[x0] : 0.f;
                    float v01 = vx1 ? xp0[x0 + 1] : 0.f;
                    float v10 = vx0 ? xp1[x0] : 0.f;
                    float v11 = vx1 ? xp1[x0 + 1] : 0.f;
                    v = fy0 * ((1.f - wx) * v00 + wx * v01)
                      + fy1 * ((1.f - wx) * v10 + wx * v11);
                }
                sv[ci][wp] = v;
            }
        } else {
            for (int wp = lane; wp < HP; wp += 32) sv[ci][wp] = 0.f;
        }
    }
    __syncthreads();

    // phase 2: coalesced tf32 power stores (consecutive tid -> consecutive k)
    const size_t base = (size_t)blockIdx.x * HP * KPT;
    for (int idx = tid; idx < HP * KPT; idx += 256) {
        const int wp = idx / KPT;
        const int k = idx - wp * KPT;
        const int q = k >> 6;
        const int ci = k & 63;
        const float v = sv[ci][wp];
        const float p = (q == 0) ? v : (q == 1 ? v * v : v * v * v);
        g_P[base + idx] = round_tf32(p);
    }
}

// ---------------------------------------------------------------------------
// Kernel 2: weight matrix prep, K ordered (tap, q, ci), tf32-rounded
// ---------------------------------------------------------------------------
__global__ void bprep_kernel(const float* __restrict__ w) {
    int idx = blockIdx.x * blockDim.x + threadIdx.x;
    if (idx >= COUT * KTOT) return;
    int co = idx / KTOT;
    int kk = idx % KTOT;
    int tap = kk / KPT;
    int k2 = kk % KPT;
    int q = k2 >> 6;
    int ci = k2 & 63;
    int ky = tap / 3;
    int kx = tap % 3;
    g_B[idx] = round_tf32(
        w[(((size_t)co * (3 * CIN) + q * CIN + ci) * 3 + ky) * 3 + kx]);
}

// ---------------------------------------------------------------------------
// Kernel 3: implicit-GEMM conv via mma.sync tf32 (HMMA).
// CTA: 128(M) x 128(N), K-chunks of 32, 3-stage cp.async pipeline,
// ONE __syncthreads per chunk. 8 warps as 2(M) x 4(N); warp tile 64x32.
// ---------------------------------------------------------------------------
__global__ void __launch_bounds__(256, 2)
gemm_kernel(const float* __restrict__ bias, float* __restrict__ out) {
    extern __shared__ float smem[];
    const uint32_t sbase = smem_u32(smem);
    const int tid = threadIdx.x;
    const int lane = tid & 31;
    const int wid = tid >> 5;
    const long long m0 = (long long)blockIdx.x * MT;

    const int warpM = (wid >> 2) * 64;
    const int warpN = (wid & 3) * 32;

    // ldmatrix per-thread source coordinates
    const int rowA = ((lane >> 3) & 1) * 8 + (lane & 7);
    const int colA = (lane >> 4) * 4;
    const uint32_t aAddr0 = sbase + (uint32_t)(((warpM + rowA) * PITCH + colA) * 4);
    const int rowB = lane & 7;
    const int colB = ((lane >> 3) & 1) * 4;
    const uint32_t bAddr0 = sbase + (uint32_t)(A_TILE_F * 4) +
                            (uint32_t)(((warpN + rowB) * PITCH + colB) * 4);

    // cp.async per-thread coordinates: row 0..127, half 0..1 (4 chunks each)
    const int rr = tid & 127;
    const int khalf = (tid >> 7) * 4;

    float acc[4][4][4];
#pragma unroll
    for (int i = 0; i < 4; ++i)
#pragma unroll
        for (int j = 0; j < 4; ++j)
#pragma unroll
            for (int k = 0; k < 4; ++k) acc[i][j][k] = 0.f;

    // -------- stage loader: one K=32 chunk (A 128x32 + B 128x32) --------
    auto load_chunk = [&](int c, int s) {
        const int tap = c / 6;
        const int inner = (c % 6) * KC;
        const int toff = (tap / 3 - 1) * HP + (tap % 3 - 1);
        const uint32_t dA = sbase + (uint32_t)(s * STAGE_F * 4);
        const uint32_t dB = dA + (uint32_t)(A_TILE_F * 4);

        long long grow = m0 + rr + toff;
        bool ok = (grow >= 0) && (grow < (long long)MPAD);
        const float* srcA = g_P + (ok ? grow : 0) * KPT + inner;
        const float* srcB = g_B + (size_t)rr * KTOT + c * KC;
#pragma unroll
        for (int j = 0; j < 4; ++j) {
            const int kc = khalf + j;
            cp16(dA + (uint32_t)((rr * PITCH + kc * 4) * 4), srcA + kc * 4,
                 ok ? 16u : 0u);
            cp16(dB + (uint32_t)((rr * PITCH + kc * 4) * 4), srcB + kc * 4, 16u);
        }
        CP_COMMIT();
    };

    // prologue: stages 0..1
#pragma unroll
    for (int s = 0; s < STAGES - 1; ++s) load_chunk(s, s);

    // -------- main loop: ONE sync per chunk --------
    int sidx = 0;        // c % 3
    int pidx = 2;        // (c+2) % 3
#pragma unroll 1
    for (int c = 0; c < NCHUNK; ++c) {
        CP_WAIT1();           // stage c's data has landed
        __syncthreads();      // all warps done reading stage (c-1)%3

        const int cpre = c + STAGES - 1;
        if (cpre < NCHUNK) load_chunk(cpre, pidx);  // overwrites (c-1)%3: safe
        else CP_COMMIT();                           // keep group accounting

        const uint32_t soff = (uint32_t)(sidx * STAGE_F * 4);
        const uint32_t sa = aAddr0 + soff;
        const uint32_t sb = bAddr0 + soff;

#pragma unroll
        for (int ks = 0; ks < 4; ++ks) {
            const uint32_t koff = (uint32_t)(ks * 8 * 4);
            uint32_t b0[4], b1[4];
#pragma unroll
            for (int nt = 0; nt < 4; ++nt)
                LDSM_X2(b0[nt], b1[nt], sb + (uint32_t)(nt * 8 * PITCH * 4) + koff);
#pragma unroll
            for (int mt = 0; mt < 4; ++mt) {
                uint32_t a0, a1, a2, a3;
                LDSM_X4(a0, a1, a2, a3, sa + (uint32_t)(mt * 16 * PITCH * 4) + koff);
#pragma unroll
                for (int nt = 0; nt < 4; ++nt)
                    MMA_TF32(acc[mt][nt], a0, a1, a2, a3, b0[nt], b1[nt]);
            }
        }
        sidx = (sidx == 2) ? 0 : sidx + 1;
        pidx = (pidx == 2) ? 0 : pidx + 1;
    }

    // -------- epilogue --------
#pragma unroll
    for (int mt = 0; mt < 4; ++mt) {
#pragma unroll
        for (int half = 0; half < 2; ++half) {
            long long m = m0 + warpM + mt * 16 + (lane >> 2) + half * 8;
            if (m >= (long long)MPAD) continue;
            int mi = (int)m;
            int nb = mi / HP2;
            int rem = mi % HP2;
            int hp = rem / HP;
            int wp = rem % HP;
            if (hp < 1 || hp > HH || wp < 1 || wp > WW) continue;
            float* op = out + (((size_t)nb * COUT) * HH + (hp - 1)) * WW + (wp - 1);
#pragma unroll
            for (int nt = 0; nt < 4; ++nt) {
                int co = warpN + nt * 8 + 2 * (lane & 3);
                op[(size_t)co * (HH * WW)] =
                    acc[mt][nt][half * 2 + 0] + __ldg(bias + co);
                op[(size_t)(co + 1) * (HH * WW)] =
                    acc[mt][nt][half * 2 + 1] + __ldg(bias + co + 1);
            }
        }
    }
}

// ---------------------------------------------------------------------------
extern "C" void kernel_launch(void* const* d_in, const int* in_sizes, int n_in,
                              void* d_out, int out_size) {
    const float* x = (const float*)d_in[0];
    const float* weights = (const float*)d_in[1];
    const float* bias = (const float*)d_in[2];
    const float* shifts = (const float*)d_in[3];
    float* out = (float*)d_out;

    pbuild_kernel<<<NB * HP, 256>>>(x, shifts);
    bprep_kernel<<<(COUT * KTOT + 255) / 256, 256>>>(weights);

    cudaFuncSetAttribute(gemm_kernel,
                         cudaFuncAttributeMaxDynamicSharedMemorySize,
                         SMEM_BYTES);
    const int grid = (MPAD + MT - 1) / MT;  // 1625
    gemm_kernel<<<grid, 256, SMEM_BYTES>>>(bias, out);
}

// round 10
// speedup vs baseline: 1.5024x; 1.3715x over previous
#include <cuda_runtime.h>
#include <cstdint>

#define NB 16
#define CIN 64
#define HH 112
#define WW 112
#define COUT 128
#define HP 114                       // padded spatial (1-pixel halo)
#define HP2 (HP * HP)                // 12996
#define MPAD (NB * HP2)              // 207936 GEMM rows
#define KPT 192                      // K per tap (3 powers x 64 ci)
#define KTOT 1728                    // 9 taps * 192
#define KC 16                        // K per pipeline chunk
#define NCHUNK 108                   // 1728 / 16
#define STAGES 5
#define PITCH 20                     // floats per smem tile row (80B)
#define MT 128
#define A_TILE_F (MT * PITCH)
#define STAGE_F (2 * A_TILE_F)       // A + B = 5120 floats = 20480 B
#define SMEM_BYTES (STAGES * STAGE_F * 4)  // 102400

// scratch: padded tf32 powers matrix and tf32 weight matrix
__device__ __align__(128) float g_P[(size_t)MPAD * KPT];   // [m][q*64+ci]
__device__ __align__(128) float g_B[(size_t)COUT * KTOT];  // [co][tap*192+q*64+ci]

// ---------------------------------------------------------------------------
// PTX helpers (base PTX only — harness ptxas targets sm_103 family)
// ---------------------------------------------------------------------------
__device__ __forceinline__ uint32_t smem_u32(const void* p) {
    uint32_t a;
    asm("{ .reg .u64 t; cvta.to.shared.u64 t, %1; cvt.u32.u64 %0, t; }"
        : "=r"(a) : "l"(p));
    return a;
}

__device__ __forceinline__ void cp16(uint32_t dst, const void* src, uint32_t sz) {
    asm volatile("cp.async.cg.shared.global [%0], [%1], 16, %2;"
                 :: "r"(dst), "l"(src), "r"(sz) : "memory");
}

#define CP_COMMIT() asm volatile("cp.async.commit_group;" ::: "memory")
#define CP_WAIT3()  asm volatile("cp.async.wait_group 3;" ::: "memory")

#define LDSM_X4(r0, r1, r2, r3, addr)                                         \
    asm volatile("ldmatrix.sync.aligned.m8n8.x4.shared.b16 {%0,%1,%2,%3}, [%4];" \
                 : "=r"(r0), "=r"(r1), "=r"(r2), "=r"(r3) : "r"(addr))

#define LDSM_X2(r0, r1, addr)                                                 \
    asm volatile("ldmatrix.sync.aligned.m8n8.x2.shared.b16 {%0,%1}, [%2];"    \
                 : "=r"(r0), "=r"(r1) : "r"(addr))

#define MMA_TF32(c, a0, a1, a2, a3, b0, b1)                                   \
    asm volatile(                                                             \
        "mma.sync.aligned.m16n8k8.row.col.f32.tf32.tf32.f32 "                 \
        "{%0,%1,%2,%3}, {%4,%5,%6,%7}, {%8,%9}, {%0,%1,%2,%3};"               \
        : "+f"((c)[0]), "+f"((c)[1]), "+f"((c)[2]), "+f"((c)[3])              \
        : "r"(a0), "r"(a1), "r"(a2), "r"(a3), "r"(b0), "r"(b1))

__device__ __forceinline__ float round_tf32(float v) {
    uint32_t t;
    asm("cvt.rna.tf32.f32 %0, %1;" : "=r"(t) : "f"(v));
    return __uint_as_float(t);
}

// ---------------------------------------------------------------------------
// Kernel 1: fused bilinear shift + Maclaurin powers into padded tf32 matrix P.
// Block = (n, hp). Warp owns ci rows (params computed per-ci); lanes sweep wp
// -> coalesced image loads. (R9-proven: 67us)
// ---------------------------------------------------------------------------
__global__ void __launch_bounds__(256)
pbuild_kernel(const float* __restrict__ x, const float* __restrict__ shifts) {
    __shared__ float sv[CIN][HP + 3];   // pitch 117 (odd) -> no conflicts
    const int tid = threadIdx.x;
    const int lane = tid & 31;
    const int wid = tid >> 5;
    const int hp = blockIdx.x % HP;
    const int n = blockIdx.x / HP;
    const bool row_live = (hp >= 1) && (hp <= HH);

    for (int ci = wid; ci < CIN; ci += 8) {
        if (row_live) {
            const float sx = shifts[ci * 2 + 0] * 4.0f;
            const float sy = shifts[ci * 2 + 1] * 4.0f;
            const float iy = (float)(hp - 1) + sy;
            const float y0f = floorf(iy);
            const float wy = iy - y0f;
            const int y0 = (int)y0f;
            const bool vy0 = (y0 >= 0) && (y0 < HH);
            const bool vy1 = (y0 + 1 >= 0) && (y0 + 1 < HH);
            const float* xp0 =
                x + ((size_t)(n * CIN + ci) * HH + (vy0 ? y0 : 0)) * WW;
            const float* xp1 =
                x + ((size_t)(n * CIN + ci) * HH + (vy1 ? y0 + 1 : 0)) * WW;
            const float fy0 = vy0 ? (1.f - wy) : 0.f;
            const float fy1 = vy1 ? wy : 0.f;

            for (int wp = lane; wp < HP; wp += 32) {
                float v = 0.f;
                if (wp >= 1 && wp <= WW) {
                    const float jx = (float)(wp - 1) + sx;
                    const float x0f = floorf(jx);
                    const float wx = jx - x0f;
                    const int x0 = (int)x0f;
                    const bool vx0 = (x0 >= 0) && (x0 < WW);
                    const bool vx1 = (x0 + 1 >= 0) && (x0 + 1 < WW);
                    float v00 = vx0 ? xp0[x0] : 0.f;
                    float v01 = vx1 ? xp0[x0 + 1] : 0.f;
                    float v10 = vx0 ? xp1[x0] : 0.f;
                    float v11 = vx1 ? xp1[x0 + 1] : 0.f;
                    v = fy0 * ((1.f - wx) * v00 + wx * v01)
                      + fy1 * ((1.f - wx) * v10 + wx * v11);
                }
                sv[ci][wp] = v;
            }
        } else {
            for (int wp = lane; wp < HP; wp += 32) sv[ci][wp] = 0.f;
        }
    }
    __syncthreads();

    // phase 2: coalesced tf32 power stores
    const size_t base = (size_t)blockIdx.x * HP * KPT;
    for (int idx = tid; idx < HP * KPT; idx += 256) {
        const int wp = idx / KPT;
        const int k = idx - wp * KPT;
        const int q = k >> 6;
        const int ci = k & 63;
        const float v = sv[ci][wp];
        const float p = (q == 0) ? v : (q == 1 ? v * v : v * v * v);
        g_P[base + idx] = round_tf32(p);
    }
}

// ---------------------------------------------------------------------------
// Kernel 2: weight matrix prep, K ordered (tap, q, ci), tf32-rounded
// ---------------------------------------------------------------------------
__global__ void bprep_kernel(const float* __restrict__ w) {
    int idx = blockIdx.x * blockDim.x + threadIdx.x;
    if (idx >= COUT * KTOT) return;
    int co = idx / KTOT;
    int kk = idx % KTOT;
    int tap = kk / KPT;
    int k2 = kk % KPT;
    int q = k2 >> 6;
    int ci = k2 & 63;
    int ky = tap / 3;
    int kx = tap % 3;
    g_B[idx] = round_tf32(
        w[(((size_t)co * (3 * CIN) + q * CIN + ci) * 3 + ky) * 3 + kx]);
}

// ---------------------------------------------------------------------------
// Kernel 3: implicit-GEMM conv via mma.sync tf32 (HMMA).
// CTA: 128(M) x 128(N), K-chunks of 16, 5-stage cp.async pipeline with
// wait_group 3 (48KB in flight), ONE __syncthreads per chunk.
// 8 warps as 2(M) x 4(N); warp tile 64x32. R4's coalesced loader.
// ---------------------------------------------------------------------------
__global__ void __launch_bounds__(256, 2)
gemm_kernel(const float* __restrict__ bias, float* __restrict__ out) {
    extern __shared__ float smem[];
    const uint32_t sbase = smem_u32(smem);
    const int tid = threadIdx.x;
    const int lane = tid & 31;
    const int wid = tid >> 5;
    const long long m0 = (long long)blockIdx.x * MT;

    const int warpM = (wid >> 2) * 64;
    const int warpN = (wid & 3) * 32;

    // ldmatrix per-thread source coordinates
    const int rowA = ((lane >> 3) & 1) * 8 + (lane & 7);
    const int colA = (lane >> 4) * 4;
    const uint32_t aAddr0 = sbase + (uint32_t)(((warpM + rowA) * PITCH + colA) * 4);
    const int rowB = lane & 7;
    const int colB = ((lane >> 3) & 1) * 4;
    const uint32_t bAddr0 = sbase + (uint32_t)(A_TILE_F * 4) +
                            (uint32_t)(((warpN + rowB) * PITCH + colB) * 4);

    // cp.async per-thread coordinates (R4 coalesced pattern):
    // 4 consecutive lanes cover 64B contiguous of one row.
    const int r0 = tid >> 2, kc0 = tid & 3;
    const int r1 = r0 + 64;

    float acc[4][4][4];
#pragma unroll
    for (int i = 0; i < 4; ++i)
#pragma unroll
        for (int j = 0; j < 4; ++j)
#pragma unroll
            for (int k = 0; k < 4; ++k) acc[i][j][k] = 0.f;

    // -------- stage loader: one K=16 chunk (A 128x16 + B 128x16) --------
    auto load_chunk = [&](int c, int s) {
        const int tap = c / 12;
        const int inner = (c % 12) * KC;
        const int toff = (tap / 3 - 1) * HP + (tap % 3 - 1);
        const uint32_t dA = sbase + (uint32_t)(s * STAGE_F * 4);
        const uint32_t dB = dA + (uint32_t)(A_TILE_F * 4);

        {
            long long grow = m0 + r0 + toff;
            bool ok = (grow >= 0) && (grow < (long long)MPAD);
            const float* src = g_P + (ok ? grow : 0) * KPT + inner + kc0 * 4;
            cp16(dA + (uint32_t)((r0 * PITCH + kc0 * 4) * 4), src, ok ? 16u : 0u);
            cp16(dB + (uint32_t)((r0 * PITCH + kc0 * 4) * 4),
                 g_B + (size_t)r0 * KTOT + c * KC + kc0 * 4, 16u);
        }
        {
            long long grow = m0 + r1 + toff;
            bool ok = (grow >= 0) && (grow < (long long)MPAD);
            const float* src = g_P + (ok ? grow : 0) * KPT + inner + kc0 * 4;
            cp16(dA + (uint32_t)((r1 * PITCH + kc0 * 4) * 4), src, ok ? 16u : 0u);
            cp16(dB + (uint32_t)((r1 * PITCH + kc0 * 4) * 4),
                 g_B + (size_t)r1 * KTOT + c * KC + kc0 * 4, 16u);
        }
        CP_COMMIT();
    };

    // prologue: stages 0..3
#pragma unroll
    for (int s = 0; s < STAGES - 1; ++s) load_chunk(s, s);

    // -------- main loop: ONE sync per chunk, 3 chunks in flight --------
    int sidx = 0;        // c % 5
    int pidx = 4;        // (c+4) % 5
#pragma unroll 1
    for (int c = 0; c < NCHUNK; ++c) {
        CP_WAIT3();           // chunk c's data has landed (<=3 pending)
        __syncthreads();      // all warps done reading stage (c-1)%5

        const int cpre = c + STAGES - 1;
        if (cpre < NCHUNK) load_chunk(cpre, pidx);  // overwrites (c-1)%5: safe
        else CP_COMMIT();                           // keep group accounting

        const uint32_t soff = (uint32_t)(sidx * STAGE_F * 4);
        const uint32_t sa = aAddr0 + soff;
        const uint32_t sb = bAddr0 + soff;

#pragma unroll
        for (int ks = 0; ks < 2; ++ks) {
            const uint32_t koff = (uint32_t)(ks * 8 * 4);
            uint32_t b0[4], b1[4];
#pragma unroll
            for (int nt = 0; nt < 4; ++nt)
                LDSM_X2(b0[nt], b1[nt], sb + (uint32_t)(nt * 8 * PITCH * 4) + koff);
#pragma unroll
            for (int mt = 0; mt < 4; ++mt) {
                uint32_t a0, a1, a2, a3;
                LDSM_X4(a0, a1, a2, a3, sa + (uint32_t)(mt * 16 * PITCH * 4) + koff);
#pragma unroll
                for (int nt = 0; nt < 4; ++nt)
                    MMA_TF32(acc[mt][nt], a0, a1, a2, a3, b0[nt], b1[nt]);
            }
        }
        sidx = (sidx == STAGES - 1) ? 0 : sidx + 1;
        pidx = (pidx == STAGES - 1) ? 0 : pidx + 1;
    }

    // -------- epilogue --------
#pragma unroll
    for (int mt = 0; mt < 4; ++mt) {
#pragma unroll
        for (int half = 0; half < 2; ++half) {
            long long m = m0 + warpM + mt * 16 + (lane >> 2) + half * 8;
            if (m >= (long long)MPAD) continue;
            int mi = (int)m;
            int nb = mi / HP2;
            int rem = mi % HP2;
            int hp = rem / HP;
            int wp = rem % HP;
            if (hp < 1 || hp > HH || wp < 1 || wp > WW) continue;
            float* op = out + (((size_t)nb * COUT) * HH + (hp - 1)) * WW + (wp - 1);
#pragma unroll
            for (int nt = 0; nt < 4; ++nt) {
                int co = warpN + nt * 8 + 2 * (lane & 3);
                op[(size_t)co * (HH * WW)] =
                    acc[mt][nt][half * 2 + 0] + __ldg(bias + co);
                op[(size_t)(co + 1) * (HH * WW)] =
                    acc[mt][nt][half * 2 + 1] + __ldg(bias + co + 1);
            }
        }
    }
}

// ---------------------------------------------------------------------------
extern "C" void kernel_launch(void* const* d_in, const int* in_sizes, int n_in,
                              void* d_out, int out_size) {
    const float* x = (const float*)d_in[0];
    const float* weights = (const float*)d_in[1];
    const float* bias = (const float*)d_in[2];
    const float* shifts = (const float*)d_in[3];
    float* out = (float*)d_out;

    pbuild_kernel<<<NB * HP, 256>>>(x, shifts);
    bprep_kernel<<<(COUT * KTOT + 255) / 256, 256>>>(weights);

    cudaFuncSetAttribute(gemm_kernel,
                         cudaFuncAttributeMaxDynamicSharedMemorySize,
                         SMEM_BYTES);
    const int grid = (MPAD + MT - 1) / MT;  // 1625
    gemm_kernel<<<grid, 256, SMEM_BYTES>>>(bias, out);
}

// round 11
// speedup vs baseline: 2.4164x; 1.6083x over previous
#include <cuda_runtime.h>
#include <cuda_fp16.h>
#include <cstdint>

#define NB 16
#define CIN 64
#define HH 112
#define WW 112
#define COUT 128
#define HP 114                       // padded spatial (1-pixel halo)
#define HP2 (HP * HP)                // 12996
#define MPAD (NB * HP2)              // 207936 GEMM rows
#define KPT 192                      // K per tap (3 powers x 64 ci), halves
#define KTOT 1728                    // 9 taps * 192
#define KC 16                        // K halves per pipeline chunk
#define NCHUNK 108                   // 1728 / 16
#define STAGES 4
#define PITCH 24                     // halves per smem tile row (48 B)
#define MT 128
#define A_TILE_H (MT * PITCH)        // halves per A (or B) tile
#define STAGE_H (2 * A_TILE_H)       // A + B = 6144 halves = 12288 B
#define SMEM_BYTES (STAGES * STAGE_H * 2)  // 49152

// scratch: padded fp16 powers matrix and fp16 weight matrix
__device__ __align__(128) __half g_P[(size_t)MPAD * KPT];   // [m][q*64+ci]
__device__ __align__(128) __half g_B[(size_t)COUT * KTOT];  // [co][tap*192+q*64+ci]

// ---------------------------------------------------------------------------
// PTX helpers (base PTX only — harness ptxas targets sm_103 family)
// ---------------------------------------------------------------------------
__device__ __forceinline__ uint32_t smem_u32(const void* p) {
    uint32_t a;
    asm("{ .reg .u64 t; cvta.to.shared.u64 t, %1; cvt.u32.u64 %0, t; }"
        : "=r"(a) : "l"(p));
    return a;
}

__device__ __forceinline__ void cp16(uint32_t dst, const void* src, uint32_t sz) {
    asm volatile("cp.async.cg.shared.global [%0], [%1], 16, %2;"
                 :: "r"(dst), "l"(src), "r"(sz) : "memory");
}

#define CP_COMMIT() asm volatile("cp.async.commit_group;" ::: "memory")
#define CP_WAIT3()  asm volatile("cp.async.wait_group 3;" ::: "memory")

#define LDSM_X4(r0, r1, r2, r3, addr)                                         \
    asm volatile("ldmatrix.sync.aligned.m8n8.x4.shared.b16 {%0,%1,%2,%3}, [%4];" \
                 : "=r"(r0), "=r"(r1), "=r"(r2), "=r"(r3) : "r"(addr))

#define LDSM_X2(r0, r1, addr)                                                 \
    asm volatile("ldmatrix.sync.aligned.m8n8.x2.shared.b16 {%0,%1}, [%2];"    \
                 : "=r"(r0), "=r"(r1) : "r"(addr))

// fp16 inputs, fp32 accumulators
#define MMA_F16(c, a0, a1, a2, a3, b0, b1)                                    \
    asm volatile(                                                             \
        "mma.sync.aligned.m16n8k16.row.col.f32.f16.f16.f32 "                  \
        "{%0,%1,%2,%3}, {%4,%5,%6,%7}, {%8,%9}, {%0,%1,%2,%3};"               \
        : "+f"((c)[0]), "+f"((c)[1]), "+f"((c)[2]), "+f"((c)[3])              \
        : "r"(a0), "r"(a1), "r"(a2), "r"(a3), "r"(b0), "r"(b1))

// ---------------------------------------------------------------------------
// Kernel 1: fused bilinear shift + Maclaurin powers into padded fp16 matrix P.
// Block = (n, hp). Warp owns ci rows (params computed per-ci); lanes sweep wp
// -> coalesced image loads. (R9-proven structure)
// ---------------------------------------------------------------------------
__global__ void __launch_bounds__(256)
pbuild_kernel(const float* __restrict__ x, const float* __restrict__ shifts) {
    __shared__ float sv[CIN][HP + 3];   // pitch 117 (odd) -> no conflicts
    const int tid = threadIdx.x;
    const int lane = tid & 31;
    const int wid = tid >> 5;
    const int hp = blockIdx.x % HP;
    const int n = blockIdx.x / HP;
    const bool row_live = (hp >= 1) && (hp <= HH);

    for (int ci = wid; ci < CIN; ci += 8) {
        if (row_live) {
            const float sx = shifts[ci * 2 + 0] * 4.0f;
            const float sy = shifts[ci * 2 + 1] * 4.0f;
            const float iy = (float)(hp - 1) + sy;
            const float y0f = floorf(iy);
            const float wy = iy - y0f;
            const int y0 = (int)y0f;
            const bool vy0 = (y0 >= 0) && (y0 < HH);
            const bool vy1 = (y0 + 1 >= 0) && (y0 + 1 < HH);
            const float* xp0 =
                x + ((size_t)(n * CIN + ci) * HH + (vy0 ? y0 : 0)) * WW;
            const float* xp1 =
                x + ((size_t)(n * CIN + ci) * HH + (vy1 ? y0 + 1 : 0)) * WW;
            const float fy0 = vy0 ? (1.f - wy) : 0.f;
            const float fy1 = vy1 ? wy : 0.f;

            for (int wp = lane; wp < HP; wp += 32) {
                float v = 0.f;
                if (wp >= 1 && wp <= WW) {
                    const float jx = (float)(wp - 1) + sx;
                    const float x0f = floorf(jx);
                    const float wx = jx - x0f;
                    const int x0 = (int)x0f;
                    const bool vx0 = (x0 >= 0) && (x0 < WW);
                    const bool vx1 = (x0 + 1 >= 0) && (x0 + 1 < WW);
                    float v00 = vx0 ? xp0[x0] : 0.f;
                    float v01 = vx1 ? xp0[x0 + 1] : 0.f;
                    float v10 = vx0 ? xp1[x0] : 0.f;
                    float v11 = vx1 ? xp1[x0 + 1] : 0.f;
                    v = fy0 * ((1.f - wx) * v00 + wx * v01)
                      + fy1 * ((1.f - wx) * v10 + wx * v11);
                }
                sv[ci][wp] = v;
            }
        } else {
            for (int wp = lane; wp < HP; wp += 32) sv[ci][wp] = 0.f;
        }
    }
    __syncthreads();

    // phase 2: coalesced fp16 power stores
    const size_t base = (size_t)blockIdx.x * HP * KPT;
    for (int idx = tid; idx < HP * KPT; idx += 256) {
        const int wp = idx / KPT;
        const int k = idx - wp * KPT;
        const int q = k >> 6;
        const int ci = k & 63;
        const float v = sv[ci][wp];
        const float p = (q == 0) ? v : (q == 1 ? v * v : v * v * v);
        g_P[base + idx] = __float2half_rn(p);
    }
}

// ---------------------------------------------------------------------------
// Kernel 2: weight matrix prep, K ordered (tap, q, ci), fp16
// ---------------------------------------------------------------------------
__global__ void bprep_kernel(const float* __restrict__ w) {
    int idx = blockIdx.x * blockDim.x + threadIdx.x;
    if (idx >= COUT * KTOT) return;
    int co = idx / KTOT;
    int kk = idx % KTOT;
    int tap = kk / KPT;
    int k2 = kk % KPT;
    int q = k2 >> 6;
    int ci = k2 & 63;
    int ky = tap / 3;
    int kx = tap % 3;
    g_B[idx] = __float2half_rn(
        w[(((size_t)co * (3 * CIN) + q * CIN + ci) * 3 + ky) * 3 + kx]);
}

// ---------------------------------------------------------------------------
// Kernel 3: implicit-GEMM conv via mma.sync m16n8k16 fp16 (fp32 accum).
// CTA: 128(M) x 128(N), K-chunks of 16 halves, 4-stage cp.async pipeline
// (wait_group 3 -> 3 chunks in flight), R4-proven dual-sync ordering.
// 8 warps as 2(M) x 4(N); warp tile 64x32: 4 LDSM_X4 + 4 LDSM_X2 + 16 MMA.
// ---------------------------------------------------------------------------
__global__ void __launch_bounds__(256, 2)
gemm_kernel(const float* __restrict__ bias, float* __restrict__ out) {
    extern __shared__ __half smem[];
    const uint32_t sbase = smem_u32(smem);
    const int tid = threadIdx.x;
    const int lane = tid & 31;
    const int wid = tid >> 5;
    const long long m0 = (long long)blockIdx.x * MT;

    const int warpM = (wid >> 2) * 64;
    const int warpN = (wid & 3) * 32;

    // ldmatrix per-thread source coordinates (16x16 A tiles, 8x16 B tiles)
    // A x4: tile = lane>>3; row = (tile&1)*8 + (lane&7); kseg = (tile>>1)*8
    const int aRow = ((lane >> 3) & 1) * 8 + (lane & 7);
    const int aKseg = (lane >> 4) * 8;
    const uint32_t aAddr0 =
        sbase + (uint32_t)(((warpM + aRow) * PITCH + aKseg) * 2);
    // B x2: tile = (lane>>3)&1; row = lane&7; kseg = tile*8 (lanes 16-31 dup)
    const int bRow = lane & 7;
    const int bKseg = ((lane >> 3) & 1) * 8;
    const uint32_t bAddr0 = sbase + (uint32_t)(A_TILE_H * 2) +
                            (uint32_t)(((warpN + bRow) * PITCH + bKseg) * 2);

    // cp.async per-thread coordinates: row = tid>>1 (0..127), seg = tid&1
    const int rr = tid >> 1;
    const int seg = tid & 1;          // 16B segment within 32B row

    float acc[4][4][4];
#pragma unroll
    for (int i = 0; i < 4; ++i)
#pragma unroll
        for (int j = 0; j < 4; ++j)
#pragma unroll
            for (int k = 0; k < 4; ++k) acc[i][j][k] = 0.f;

    // -------- stage loader: one K=16 chunk (A 128x16h + B 128x16h) --------
    auto load_chunk = [&](int c, int s) {
        const int tap = c / 12;
        const int inner = (c % 12) * KC;
        const int toff = (tap / 3 - 1) * HP + (tap % 3 - 1);
        const uint32_t dA = sbase + (uint32_t)(s * STAGE_H * 2);
        const uint32_t dB = dA + (uint32_t)(A_TILE_H * 2);

        long long grow = m0 + rr + toff;
        bool ok = (grow >= 0) && (grow < (long long)MPAD);
        const __half* srcA = g_P + (ok ? grow : 0) * KPT + inner + seg * 8;
        cp16(dA + (uint32_t)((rr * PITCH + seg * 8) * 2), srcA, ok ? 16u : 0u);
        cp16(dB + (uint32_t)((rr * PITCH + seg * 8) * 2),
             g_B + (size_t)rr * KTOT + c * KC + seg * 8, 16u);
        CP_COMMIT();
    };

    // prologue: stages 0..2
#pragma unroll
    for (int s = 0; s < STAGES - 1; ++s) load_chunk(s, s);

    // -------- main loop (R4 ordering: load-next, wait, sync, mma, sync) ----
#pragma unroll 1
    for (int c = 0; c < NCHUNK; ++c) {
        const int cpre = c + STAGES - 1;
        if (cpre < NCHUNK) load_chunk(cpre, cpre & (STAGES - 1));
        else CP_COMMIT();
        CP_WAIT3();
        __syncthreads();

        const uint32_t soff = (uint32_t)((c & (STAGES - 1)) * STAGE_H * 2);
        const uint32_t sa = aAddr0 + soff;
        const uint32_t sb = bAddr0 + soff;

        uint32_t b0[4], b1[4];
#pragma unroll
        for (int nt = 0; nt < 4; ++nt)
            LDSM_X2(b0[nt], b1[nt], sb + (uint32_t)(nt * 8 * PITCH * 2));
#pragma unroll
        for (int mt = 0; mt < 4; ++mt) {
            uint32_t a0, a1, a2, a3;
            LDSM_X4(a0, a1, a2, a3, sa + (uint32_t)(mt * 16 * PITCH * 2));
#pragma unroll
            for (int nt = 0; nt < 4; ++nt)
                MMA_F16(acc[mt][nt], a0, a1, a2, a3, b0[nt], b1[nt]);
        }
        __syncthreads();
    }

    // -------- epilogue --------
#pragma unroll
    for (int mt = 0; mt < 4; ++mt) {
#pragma unroll
        for (int half = 0; half < 2; ++half) {
            long long m = m0 + warpM + mt * 16 + (lane >> 2) + half * 8;
            if (m >= (long long)MPAD) continue;
            int mi = (int)m;
            int nb = mi / HP2;
            int rem = mi % HP2;
            int hp = rem / HP;
            int wp = rem % HP;
            if (hp < 1 || hp > HH || wp < 1 || wp > WW) continue;
            float* op = out + (((size_t)nb * COUT) * HH + (hp - 1)) * WW + (wp - 1);
#pragma unroll
            for (int nt = 0; nt < 4; ++nt) {
                int co = warpN + nt * 8 + 2 * (lane & 3);
                op[(size_t)co * (HH * WW)] =
                    acc[mt][nt][half * 2 + 0] + __ldg(bias + co);
                op[(size_t)(co + 1) * (HH * WW)] =
                    acc[mt][nt][half * 2 + 1] + __ldg(bias + co + 1);
            }
        }
    }
}

// ---------------------------------------------------------------------------
extern "C" void kernel_launch(void* const* d_in, const int* in_sizes, int n_in,
                              void* d_out, int out_size) {
    const float* x = (const float*)d_in[0];
    const float* weights = (const float*)d_in[1];
    const float* bias = (const float*)d_in[2];
    const float* shifts = (const float*)d_in[3];
    float* out = (float*)d_out;

    pbuild_kernel<<<NB * HP, 256>>>(x, shifts);
    bprep_kernel<<<(COUT * KTOT + 255) / 256, 256>>>(weights);

    cudaFuncSetAttribute(gemm_kernel,
                         cudaFuncAttributeMaxDynamicSharedMemorySize,
                         SMEM_BYTES);
    const int grid = (MPAD + MT - 1) / MT;  // 1625
    gemm_kernel<<<grid, 256, SMEM_BYTES>>>(bias, out);
}

// round 14
// speedup vs baseline: 2.7085x; 1.1209x over previous
#include <cuda_runtime.h>
#include <cuda_fp16.h>
#include <cstdint>

#define NB 16
#define CIN 64
#define HH 112
#define WW 112
#define COUT 128
#define HP 114                       // padded spatial (1-pixel halo)
#define HP2 (HP * HP)                // 12996
#define MPAD (NB * HP2)              // 207936 GEMM rows
#define KPT 192                      // K per tap (3 powers x 64 ci), halves
#define KTOT 1728                    // 9 taps * 192
#define KC 32                        // K halves per pipeline chunk (64B rows)
#define NCHUNK 54                    // 1728 / 32
#define STAGES 4
#define PITCH 40                     // halves per smem tile row (80B)
#define MT 128
#define A_TILE_H (MT * PITCH)        // halves per A (or B) tile
#define STAGE_H (2 * A_TILE_H)       // A + B = 10240 halves = 20480 B
#define SMEM_BYTES (STAGES * STAGE_H * 2)  // 81920

// scratch: padded fp16 powers matrix and fp16 weight matrix
__device__ __align__(128) __half g_P[(size_t)MPAD * KPT];   // [m][q*64+ci]
__device__ __align__(128) __half g_B[(size_t)COUT * KTOT];  // [co][tap*192+q*64+ci]

// ---------------------------------------------------------------------------
// PTX helpers (base PTX only — harness ptxas targets sm_103 family)
// ---------------------------------------------------------------------------
__device__ __forceinline__ uint32_t smem_u32(const void* p) {
    uint32_t a;
    asm("{ .reg .u64 t; cvta.to.shared.u64 t, %1; cvt.u32.u64 %0, t; }"
        : "=r"(a) : "l"(p));
    return a;
}

__device__ __forceinline__ void cp16(uint32_t dst, const void* src, uint32_t sz) {
    asm volatile("cp.async.cg.shared.global [%0], [%1], 16, %2;"
                 :: "r"(dst), "l"(src), "r"(sz) : "memory");
}

#define CP_COMMIT() asm volatile("cp.async.commit_group;" ::: "memory")
#define CP_WAIT3()  asm volatile("cp.async.wait_group 3;" ::: "memory")

#define LDSM_X4(r0, r1, r2, r3, addr)                                         \
    asm volatile("ldmatrix.sync.aligned.m8n8.x4.shared.b16 {%0,%1,%2,%3}, [%4];" \
                 : "=r"(r0), "=r"(r1), "=r"(r2), "=r"(r3) : "r"(addr))

#define LDSM_X2(r0, r1, addr)                                                 \
    asm volatile("ldmatrix.sync.aligned.m8n8.x2.shared.b16 {%0,%1}, [%2];"    \
                 : "=r"(r0), "=r"(r1) : "r"(addr))

// fp16 inputs, fp32 accumulators
#define MMA_F16(c, a0, a1, a2, a3, b0, b1)                                    \
    asm volatile(                                                             \
        "mma.sync.aligned.m16n8k16.row.col.f32.f16.f16.f32 "                  \
        "{%0,%1,%2,%3}, {%4,%5,%6,%7}, {%8,%9}, {%0,%1,%2,%3};"               \
        : "+f"((c)[0]), "+f"((c)[1]), "+f"((c)[2]), "+f"((c)[3])              \
        : "r"(a0), "r"(a1), "r"(a2), "r"(a3), "r"(b0), "r"(b1))

// ---------------------------------------------------------------------------
// Kernel 1: fused bilinear shift + Maclaurin powers into padded fp16 matrix P.
// Block = (n, hp). Phase 1: warp owns ci, lanes sweep wp (coalesced loads),
// stores sv[wp][ci] (pitch 65 -> conflict-free). Phase 2: each thread emits
// 4 consecutive fp16 of one power block as a single 8B store.
// ---------------------------------------------------------------------------
__global__ void __launch_bounds__(256)
pbuild_kernel(const float* __restrict__ x, const float* __restrict__ shifts) {
    __shared__ float sv[HP][CIN + 1];   // pitch 65 (odd) -> conflict-free
    const int tid = threadIdx.x;
    const int lane = tid & 31;
    const int wid = tid >> 5;
    const int hp = blockIdx.x % HP;
    const int n = blockIdx.x / HP;
    const bool row_live = (hp >= 1) && (hp <= HH);

    for (int ci = wid; ci < CIN; ci += 8) {
        if (row_live) {
            const float sx = shifts[ci * 2 + 0] * 4.0f;
            const float sy = shifts[ci * 2 + 1] * 4.0f;
            const float iy = (float)(hp - 1) + sy;
            const float y0f = floorf(iy);
            const float wy = iy - y0f;
            const int y0 = (int)y0f;
            const bool vy0 = (y0 >= 0) && (y0 < HH);
            const bool vy1 = (y0 + 1 >= 0) && (y0 + 1 < HH);
            const float* xp0 =
                x + ((size_t)(n * CIN + ci) * HH + (vy0 ? y0 : 0)) * WW;
            const float* xp1 =
                x + ((size_t)(n * CIN + ci) * HH + (vy1 ? y0 + 1 : 0)) * WW;
            const float fy0 = vy0 ? (1.f - wy) : 0.f;
            const float fy1 = vy1 ? wy : 0.f;

            for (int wp = lane; wp < HP; wp += 32) {
                float v = 0.f;
                if (wp >= 1 && wp <= WW) {
                    const float jx = (float)(wp - 1) + sx;
                    const float x0f = floorf(jx);
                    const float wx = jx - x0f;
                    const int x0 = (int)x0f;
                    const bool vx0 = (x0 >= 0) && (x0 < WW);
                    const bool vx1 = (x0 + 1 >= 0) && (x0 + 1 < WW);
                    float v00 = vx0 ? xp0[x0] : 0.f;
                    float v01 = vx1 ? xp0[x0 + 1] : 0.f;
                    float v10 = vx0 ? xp1[x0] : 0.f;
                    float v11 = vx1 ? xp1[x0 + 1] : 0.f;
                    v = fy0 * ((1.f - wx) * v00 + wx * v01)
                      + fy1 * ((1.f - wx) * v10 + wx * v11);
                }
                sv[wp][ci] = v;
            }
        } else {
            for (int wp = lane; wp < HP; wp += 32) sv[wp][ci] = 0.f;
        }
    }
    __syncthreads();

    // phase 2: 4 fp16 per thread per iter, single 8B store (256B/warp/instr)
    __half* pb = g_P + (size_t)blockIdx.x * HP * KPT;
    const int NQUAD = HP * (KPT / 4);  // 5472
    for (int idx = tid; idx < NQUAD; idx += 256) {
        const int wp = idx / (KPT / 4);
        const int r = idx - wp * (KPT / 4);   // 0..47
        const int q = r >> 4;                 // 0..2
        const int ci4 = (r & 15) * 4;
        const float* svr = &sv[wp][ci4];
        __half h[4];
#pragma unroll
        for (int j = 0; j < 4; ++j) {
            const float v = svr[j];
            const float p = (q == 0) ? v : (q == 1 ? v * v : v * v * v);
            h[j] = __float2half_rn(p);
        }
        *(uint2*)(pb + (size_t)wp * KPT + q * 64 + ci4) = *(const uint2*)h;
    }
}

// ---------------------------------------------------------------------------
// Kernel 2: weight matrix prep, K ordered (tap, q, ci), fp16
// ---------------------------------------------------------------------------
__global__ void bprep_kernel(const float* __restrict__ w) {
    int idx = blockIdx.x * blockDim.x + threadIdx.x;
    if (idx >= COUT * KTOT) return;
    int co = idx / KTOT;
    int kk = idx % KTOT;
    int tap = kk / KPT;
    int k2 = kk % KPT;
    int q = k2 >> 6;
    int ci = k2 & 63;
    int ky = tap / 3;
    int kx = tap % 3;
    g_B[idx] = __float2half_rn(
        w[(((size_t)co * (3 * CIN) + q * CIN + ci) * 3 + ky) * 3 + kx]);
}

// ---------------------------------------------------------------------------
// Kernel 3: implicit-GEMM conv via mma.sync m16n8k16 fp16 (fp32 accum).
// CTA: 128(M) x 128(N), K-chunks of 32 halves, 4-stage cp.async pipeline
// (wait_group 3), R4/R11-proven ordering, HALF the barrier count of R11.
// 8 warps as 2(M) x 4(N); warp tile 64x32.
// ---------------------------------------------------------------------------
__global__ void __launch_bounds__(256, 2)
gemm_kernel(const float* __restrict__ bias, float* __restrict__ out) {
    extern __shared__ __half smem[];
    const uint32_t sbase = smem_u32(smem);
    const int tid = threadIdx.x;
    const int lane = tid & 31;
    const int wid = tid >> 5;
    const long long m0 = (long long)blockIdx.x * MT;

    const int warpM = (wid >> 2) * 64;
    const int warpN = (wid & 3) * 32;

    // ldmatrix per-thread source coordinates (16x16 A tiles, 8x16 B tiles)
    const int aRow = ((lane >> 3) & 1) * 8 + (lane & 7);
    const int aKseg = (lane >> 4) * 8;
    const uint32_t aAddr0 =
        sbase + (uint32_t)(((warpM + aRow) * PITCH + aKseg) * 2);
    const int bRow = lane & 7;
    const int bKseg = ((lane >> 3) & 1) * 8;
    const uint32_t bAddr0 = sbase + (uint32_t)(A_TILE_H * 2) +
                            (uint32_t)(((warpN + bRow) * PITCH + bKseg) * 2);

    // cp.async coordinates: 4 adjacent lanes = one full 64B row (PROVEN law)
    const int r0 = tid >> 2, kc = tid & 3;   // row 0..63, 16B seg 0..3
    const int r1 = r0 + 64;

    float acc[4][4][4];
#pragma unroll
    for (int i = 0; i < 4; ++i)
#pragma unroll
        for (int j = 0; j < 4; ++j)
#pragma unroll
            for (int k = 0; k < 4; ++k) acc[i][j][k] = 0.f;

    // -------- stage loader: one K=32 chunk (A 128x32h + B 128x32h) --------
    auto load_chunk = [&](int c, int s) {
        const int tap = c / 6;
        const int inner = (c % 6) * KC;
        const int toff = (tap / 3 - 1) * HP + (tap % 3 - 1);
        const uint32_t dA = sbase + (uint32_t)(s * STAGE_H * 2);
        const uint32_t dB = dA + (uint32_t)(A_TILE_H * 2);

        {
            long long grow = m0 + r0 + toff;
            bool ok = (grow >= 0) && (grow < (long long)MPAD);
            const __half* srcA = g_P + (ok ? grow : 0) * KPT + inner + kc * 8;
            cp16(dA + (uint32_t)((r0 * PITCH + kc * 8) * 2), srcA, ok ? 16u : 0u);
            cp16(dB + (uint32_t)((r0 * PITCH + kc * 8) * 2),
                 g_B + (size_t)r0 * KTOT + c * KC + kc * 8, 16u);
        }
        {
            long long grow = m0 + r1 + toff;
            bool ok = (grow >= 0) && (grow < (long long)MPAD);
            const __half* srcA = g_P + (ok ? grow : 0) * KPT + inner + kc * 8;
            cp16(dA + (uint32_t)((r1 * PITCH + kc * 8) * 2), srcA, ok ? 16u : 0u);
            cp16(dB + (uint32_t)((r1 * PITCH + kc * 8) * 2),
                 g_B + (size_t)r1 * KTOT + c * KC + kc * 8, 16u);
        }
        CP_COMMIT();
    };

    // prologue: stages 0..2
#pragma unroll
    for (int s = 0; s < STAGES - 1; ++s) load_chunk(s, s);

    // -------- main loop (R11 ordering; 54 chunks -> 108 barriers) --------
#pragma unroll 1
    for (int c = 0; c < NCHUNK; ++c) {
        const int cpre = c + STAGES - 1;
        if (cpre < NCHUNK) load_chunk(cpre, cpre & (STAGES - 1));
        else CP_COMMIT();
        CP_WAIT3();
        __syncthreads();

        const uint32_t soff = (uint32_t)((c & (STAGES - 1)) * STAGE_H * 2);
        const uint32_t sa = aAddr0 + soff;
        const uint32_t sb = bAddr0 + soff;

#pragma unroll
        for (int ks = 0; ks < 2; ++ks) {
            const uint32_t koff = (uint32_t)(ks * 16 * 2);  // 16 halves
            uint32_t b0[4], b1[4];
#pragma unroll
            for (int nt = 0; nt < 4; ++nt)
                LDSM_X2(b0[nt], b1[nt],
                        sb + (uint32_t)(nt * 8 * PITCH * 2) + koff);
#pragma unroll
            for (int mt = 0; mt < 4; ++mt) {
                uint32_t a0, a1, a2, a3;
                LDSM_X4(a0, a1, a2, a3,
                        sa + (uint32_t)(mt * 16 * PITCH * 2) + koff);
#pragma unroll
                for (int nt = 0; nt < 4; ++nt)
                    MMA_F16(acc[mt][nt], a0, a1, a2, a3, b0[nt], b1[nt]);
            }
        }
        __syncthreads();
    }

    // -------- epilogue --------
#pragma unroll
    for (int mt = 0; mt < 4; ++mt) {
#pragma unroll
        for (int half = 0; half < 2; ++half) {
            long long m = m0 + warpM + mt * 16 + (lane >> 2) + half * 8;
            if (m >= (long long)MPAD) continue;
            int mi = (int)m;
            int nb = mi / HP2;
            int rem = mi % HP2;
            int hp = rem / HP;
            int wp = rem % HP;
            if (hp < 1 || hp > HH || wp < 1 || wp > WW) continue;
            float* op = out + (((size_t)nb * COUT) * HH + (hp - 1)) * WW + (wp - 1);
#pragma unroll
            for (int nt = 0; nt < 4; ++nt) {
                int co = warpN + nt * 8 + 2 * (lane & 3);
                op[(size_t)co * (HH * WW)] =
                    acc[mt][nt][half * 2 + 0] + __ldg(bias + co);
                op[(size_t)(co + 1) * (HH * WW)] =
                    acc[mt][nt][half * 2 + 1] + __ldg(bias + co + 1);
            }
        }
    }
}

// ---------------------------------------------------------------------------
extern "C" void kernel_launch(void* const* d_in, const int* in_sizes, int n_in,
                              void* d_out, int out_size) {
    const float* x = (const float*)d_in[0];
    const float* weights = (const float*)d_in[1];
    const float* bias = (const float*)d_in[2];
    const float* shifts = (const float*)d_in[3];
    float* out = (float*)d_out;

    pbuild_kernel<<<NB * HP, 256>>>(x, shifts);
    bprep_kernel<<<(COUT * KTOT + 255) / 256, 256>>>(weights);

    cudaFuncSetAttribute(gemm_kernel,
                         cudaFuncAttributeMaxDynamicSharedMemorySize,
                         SMEM_BYTES);
    const int grid = (MPAD + MT - 1) / MT;  // 1625
    gemm_kernel<<<grid, 256, SMEM_BYTES>>>(bias, out);
}